// round 1
// baseline (speedup 1.0000x reference)
#include <cuda_runtime.h>
#include <math.h>

#define D 128
#define H 8
#define HD 1024
#define NCIR 585
#define NDIS 88
#define ECC 20000
#define EDD 3000

// -------------------- scratch --------------------
__device__ float g_scratch[1702000];

__device__ __forceinline__ float atomicMaxFloat(float* addr, float value) {
    int* ai = (int*)addr;
    int old = *ai;
    while (__int_as_float(old) < value) {
        int assumed = old;
        old = atomicCAS(ai, assumed, __float_as_int(value));
        if (old == assumed) break;
    }
    return __int_as_float(old);
}

// -------------------- kernels --------------------

// zero/init everything a branch needs
__global__ void k_init(float* deg, float* amax, float* den, float* gatout,
                       float* ewsum, int N) {
    int i = blockIdx.x * blockDim.x + threadIdx.x;
    if (i == 0) *ewsum = 0.f;
    if (i < N) deg[i] = 1.0f;               // self-loop weight
    if (i < N * H) { amax[i] = -INFINITY; den[i] = 0.f; }
    if (i < N * HD) gatout[i] = 0.f;
}

// ew[e] = mat[src,dst]; warp-reduced sum for mean
__global__ void k_gather(const float* __restrict__ mat, const int* __restrict__ src,
                         const int* __restrict__ dst, float* __restrict__ ew,
                         float* ewsum, int E, int N) {
    int e = blockIdx.x * blockDim.x + threadIdx.x;
    float w = 0.f;
    if (e < E) {
        w = mat[src[e] * N + dst[e]];
        ew[e] = w;
    }
    #pragma unroll
    for (int off = 16; off > 0; off >>= 1) w += __shfl_down_sync(0xffffffffu, w, off);
    if ((threadIdx.x & 31) == 0 && w != 0.f) atomicAdd(ewsum, w);
}

__global__ void k_deg(const int* __restrict__ dst, const float* __restrict__ ew,
                      float* deg, int E) {
    int e = blockIdx.x * blockDim.x + threadIdx.x;
    if (e < E) atomicAdd(&deg[dst[e]], ew[e]);
}

__global__ void k_rsqrt(float* deg, int N) {
    int i = blockIdx.x * blockDim.x + threadIdx.x;
    if (i < N) deg[i] = (deg[i] > 0.f) ? rsqrtf(deg[i]) : 0.f;
}

// C[N,M] = A[N,K] @ W[K,M]
__global__ void k_gemm(const float* __restrict__ A, const float* __restrict__ W,
                       float* __restrict__ C, int N, int K, int M) {
    int idx = blockIdx.x * blockDim.x + threadIdx.x;
    if (idx >= N * M) return;
    int n = idx / M, m = idx % M;
    const float* a = A + n * K;
    float acc = 0.f;
    #pragma unroll 8
    for (int k = 0; k < K; k++) acc += a[k] * W[k * M + m];
    C[idx] = acc;
}

// out = b + h * dinv^2  (bias + self-loop term)
__global__ void k_gcn_pre(const float* __restrict__ h, const float* __restrict__ dinv,
                          const float* __restrict__ b, float* __restrict__ out, int N) {
    int idx = blockIdx.x * blockDim.x + threadIdx.x;
    if (idx >= N * D) return;
    int n = idx / D, j = idx % D;
    float di = dinv[n];
    out[idx] = b[j] + h[idx] * di * di;
}

// edge scatter: out[dst] += h[src] * norm
__global__ void k_gcn_scatter(const float* __restrict__ h, const int* __restrict__ src,
                              const int* __restrict__ dst, const float* __restrict__ ew,
                              const float* __restrict__ dinv, float* out, int E) {
    int e = blockIdx.x;
    int j = threadIdx.x;
    if (e >= E) return;
    int s = src[e], d = dst[e];
    float norm = dinv[s] * ew[e] * dinv[d];
    atomicAdd(&out[d * D + j], h[s * D + j] * norm);
}

__global__ void k_relu(float* x, int n) {
    int i = blockIdx.x * blockDim.x + threadIdx.x;
    if (i < n) x[i] = fmaxf(x[i], 0.f);
}

// per-node per-head attention dots
__global__ void k_attn_node(const float* __restrict__ h2, const float* __restrict__ aw_src,
                            const float* __restrict__ aw_dst, float* __restrict__ an_src,
                            float* __restrict__ an_dst, int N) {
    int idx = blockIdx.x * blockDim.x + threadIdx.x;
    if (idx >= N * H) return;
    int n = idx / H, hh = idx % H;
    const float* hv = h2 + n * HD + hh * D;
    const float* as = aw_src + hh * D;
    const float* ad = aw_dst + hh * D;
    float s1 = 0.f, s2 = 0.f;
    #pragma unroll 8
    for (int k = 0; k < D; k++) { float v = hv[k]; s1 += v * as[k]; s2 += v * ad[k]; }
    an_src[idx] = s1;
    an_dst[idx] = s2;
}

// c[h] = dot(We_h, a_edge_h)
__global__ void k_cvec(const float* __restrict__ we, const float* __restrict__ aedge,
                       float* __restrict__ c) {
    int hh = threadIdx.x;
    if (hh >= H) return;
    float s = 0.f;
    for (int k = 0; k < D; k++) s += we[hh * D + k] * aedge[hh * D + k];
    c[hh] = s;
}

// attention logits + segment max  (edges then self-loops)
__global__ void k_alpha(const int* __restrict__ src, const int* __restrict__ dst,
                        const float* __restrict__ ew, const float* __restrict__ ewsum,
                        const float* __restrict__ an_src, const float* __restrict__ an_dst,
                        const float* __restrict__ c, float* __restrict__ alpha,
                        float* amax, int E, int N) {
    int idx = blockIdx.x * blockDim.x + threadIdx.x;
    if (idx >= (E + N) * H) return;
    int t = idx / H, hh = idx % H;
    int s, d; float w;
    if (t < E) { s = src[t]; d = dst[t]; w = ew[t]; }
    else       { s = t - E; d = s; w = (*ewsum) / (float)E; }
    float lg = an_src[s * H + hh] + an_dst[d * H + hh] + w * c[hh];
    lg = (lg >= 0.f) ? lg : 0.2f * lg;
    alpha[idx] = lg;
    atomicMaxFloat(&amax[d * H + hh], lg);
}

// exp(logit - max) and segment sum
__global__ void k_exden(const int* __restrict__ dst, float* __restrict__ alpha,
                        const float* __restrict__ amax, float* den, int E, int N) {
    int idx = blockIdx.x * blockDim.x + threadIdx.x;
    if (idx >= (E + N) * H) return;
    int t = idx / H, hh = idx % H;
    int d = (t < E) ? dst[t] : (t - E);
    float ex = expf(alpha[idx] - amax[d * H + hh]);
    alpha[idx] = ex;
    atomicAdd(&den[d * H + hh], ex);
}

// gatout[d,h,:] += h2[s,h,:] * ex/(den+eps)
__global__ void k_gat_scatter(const float* __restrict__ h2, const int* __restrict__ src,
                              const int* __restrict__ dst, const float* __restrict__ alpha,
                              const float* __restrict__ den, float* gatout, int E, int N) {
    int t = blockIdx.x;
    int j = threadIdx.x;
    if (t >= E + N) return;
    int s, d;
    if (t < E) { s = src[t]; d = dst[t]; }
    else       { s = t - E; d = s; }
    #pragma unroll
    for (int hh = 0; hh < H; hh++) {
        float coef = alpha[t * H + hh] / (den[d * H + hh] + 1e-16f);
        atomicAdd(&gatout[d * HD + hh * D + j], h2[s * HD + hh * D + j] * coef);
    }
}

// mean over heads + bias + relu
__global__ void k_gat_final(const float* __restrict__ gatout, const float* __restrict__ b,
                            float* __restrict__ att, int N) {
    int idx = blockIdx.x * blockDim.x + threadIdx.x;
    if (idx >= N * D) return;
    int n = idx / D, j = idx % D;
    float s = 0.f;
    #pragma unroll
    for (int hh = 0; hh < H; hh++) s += gatout[n * HD + hh * D + j];
    att[idx] = fmaxf(s * 0.125f + b[j], 0.f);
}

// per-node "conv": fea[n,o] = b[o] + W0[o,:].f1[n,:] + W1[o,:].f2[n,:]
__global__ void k_cnn(const float* __restrict__ f1, const float* __restrict__ f2,
                      const float* __restrict__ cw, const float* __restrict__ cb,
                      float* __restrict__ fea, int N) {
    int idx = blockIdx.x * blockDim.x + threadIdx.x;
    if (idx >= N * 256) return;
    int n = idx / 256, o = idx % 256;
    const float* w0 = cw + (o * 2 + 0) * D;
    const float* w1 = cw + (o * 2 + 1) * D;
    const float* a = f1 + n * D;
    const float* b2 = f2 + n * D;
    float acc = cb[o];
    #pragma unroll 8
    for (int k = 0; k < D; k++) acc += w0[k] * a[k] + w1[k] * b2[k];
    fea[idx] = acc;
}

// final: out[i,j] = cir[i,:] . dis[j,:]
__global__ void k_final(const float* __restrict__ cir, const float* __restrict__ dis,
                        float* __restrict__ out) {
    int idx = blockIdx.x * blockDim.x + threadIdx.x;
    if (idx >= NCIR * NDIS) return;
    int i = idx / NDIS, j = idx % NDIS;
    const float* a = cir + i * 256;
    const float* b = dis + j * 256;
    float acc = 0.f;
    #pragma unroll 8
    for (int k = 0; k < 256; k++) acc += a[k] * b[k];
    out[idx] = acc;
}

// -------------------- host orchestration --------------------

static inline int cdiv(int a, int b) { return (a + b - 1) / b; }

static void run_branch(const float* x, const float* mat, const int* edges,
                       const float* gw1, const float* gb1,
                       const float* aw, const float* awsrc, const float* awdst,
                       const float* awedge, const float* awe, const float* ab,
                       const float* gw2, const float* gb2,
                       const float* cw, const float* cb,
                       float* fea, int N, int E, float* S) {
    // scratch layout (sized for max branch)
    float* ew     = S;
    float* dinv   = ew + 20000;
    float* h      = dinv + 640;
    float* f1     = h + 74880;
    float* att    = f1 + 74880;
    float* f2     = att + 74880;
    float* h2     = f2 + 74880;
    float* gout   = h2 + 599040;
    float* an_src = gout + 599040;
    float* an_dst = an_src + 4680;
    float* alpha  = an_dst + 4680;
    float* amax   = alpha + 164680;
    float* den    = amax + 4680;
    float* cvec   = den + 4680;
    float* ewsum  = cvec + 8;

    const int* src = edges;
    const int* dst = edges + E;
    const int TB = 256;

    k_init<<<cdiv(N * HD, TB), TB>>>(dinv /*deg in-place*/, amax, den, gout, ewsum, N);
    k_gather<<<cdiv(E, TB), TB>>>(mat, src, dst, ew, ewsum, E, N);
    k_deg<<<cdiv(E, TB), TB>>>(dst, ew, dinv, E);
    k_rsqrt<<<cdiv(N, TB), TB>>>(dinv, N);

    // GCN1
    k_gemm<<<cdiv(N * D, TB), TB>>>(x, gw1, h, N, D, D);
    k_gcn_pre<<<cdiv(N * D, TB), TB>>>(h, dinv, gb1, f1, N);
    k_gcn_scatter<<<E, D>>>(h, src, dst, ew, dinv, f1, E);
    k_relu<<<cdiv(N * D, TB), TB>>>(f1, N * D);

    // GAT
    k_gemm<<<cdiv(N * HD, TB), TB>>>(f1, aw, h2, N, D, HD);
    k_attn_node<<<cdiv(N * H, TB), TB>>>(h2, awsrc, awdst, an_src, an_dst, N);
    k_cvec<<<1, 32>>>(awe, awedge, cvec);
    k_alpha<<<cdiv((E + N) * H, TB), TB>>>(src, dst, ew, ewsum, an_src, an_dst, cvec,
                                           alpha, amax, E, N);
    k_exden<<<cdiv((E + N) * H, TB), TB>>>(dst, alpha, amax, den, E, N);
    k_gat_scatter<<<E + N, D>>>(h2, src, dst, alpha, den, gout, E, N);
    k_gat_final<<<cdiv(N * D, TB), TB>>>(gout, ab, att, N);

    // GCN2
    k_gemm<<<cdiv(N * D, TB), TB>>>(att, gw2, h, N, D, D);
    k_gcn_pre<<<cdiv(N * D, TB), TB>>>(h, dinv, gb2, f2, N);
    k_gcn_scatter<<<E, D>>>(h, src, dst, ew, dinv, f2, E);
    k_relu<<<cdiv(N * D, TB), TB>>>(f2, N * D);

    // CNN head
    k_cnn<<<cdiv(N * 256, TB), TB>>>(f1, f2, cw, cb, fea, N);
}

extern "C" void kernel_launch(void* const* d_in, const int* in_sizes, int n_in,
                              void* d_out, int out_size) {
    float* S = nullptr;
    cudaGetSymbolAddress((void**)&S, g_scratch);

    const float* x_cir     = (const float*)d_in[0];
    const float* x_dis     = (const float*)d_in[1];
    const float* cc_matrix = (const float*)d_in[2];
    const float* dd_matrix = (const float*)d_in[3];
    const float* gcn_c1_w  = (const float*)d_in[4];
    const float* gcn_c1_b  = (const float*)d_in[5];
    const float* gat_c_w   = (const float*)d_in[6];
    const float* gat_c_asrc  = (const float*)d_in[7];
    const float* gat_c_adst  = (const float*)d_in[8];
    const float* gat_c_aedge = (const float*)d_in[9];
    const float* gat_c_we  = (const float*)d_in[10];
    const float* gat_c_b   = (const float*)d_in[11];
    const float* gcn_c2_w  = (const float*)d_in[12];
    const float* gcn_c2_b  = (const float*)d_in[13];
    const float* gcn_d1_w  = (const float*)d_in[14];
    const float* gcn_d1_b  = (const float*)d_in[15];
    const float* gat_d_w   = (const float*)d_in[16];
    const float* gat_d_asrc  = (const float*)d_in[17];
    const float* gat_d_adst  = (const float*)d_in[18];
    const float* gat_d_aedge = (const float*)d_in[19];
    const float* gat_d_we  = (const float*)d_in[20];
    const float* gat_d_b   = (const float*)d_in[21];
    const float* gcn_d2_w  = (const float*)d_in[22];
    const float* gcn_d2_b  = (const float*)d_in[23];
    const float* conv_c_w  = (const float*)d_in[24];
    const float* conv_c_b  = (const float*)d_in[25];
    const float* conv_d_w  = (const float*)d_in[26];
    const float* conv_d_b  = (const float*)d_in[27];
    const int*   cc_edges  = (const int*)d_in[28];
    const int*   dd_edges  = (const int*)d_in[29];

    float* out    = (float*)d_out;
    float* cirfea = out + NCIR * NDIS;           // [585,256]
    float* disfea = cirfea + NCIR * 256;         // [88,256]

    run_branch(x_cir, cc_matrix, cc_edges,
               gcn_c1_w, gcn_c1_b,
               gat_c_w, gat_c_asrc, gat_c_adst, gat_c_aedge, gat_c_we, gat_c_b,
               gcn_c2_w, gcn_c2_b,
               conv_c_w, conv_c_b,
               cirfea, NCIR, ECC, S);

    run_branch(x_dis, dd_matrix, dd_edges,
               gcn_d1_w, gcn_d1_b,
               gat_d_w, gat_d_asrc, gat_d_adst, gat_d_aedge, gat_d_we, gat_d_b,
               gcn_d2_w, gcn_d2_b,
               conv_d_w, conv_d_b,
               disfea, NDIS, EDD, S);

    k_final<<<cdiv(NCIR * NDIS, 256), 256>>>(cirfea, disfea, out);
}

// round 3
// speedup vs baseline: 5.1573x; 5.1573x over previous
#include <cuda_runtime.h>
#include <math.h>

#define D 128
#define HD 1024
#define H 8
#define NCIR 585
#define NDIS 88
#define ECC 20000
#define EDD 3000

__device__ __align__(16) float g_scratch[1720000];

struct BP {
    // inputs
    const float *x, *mat;
    const int *edges;
    const float *gb1, *ab, *gb2, *cw, *cb;
    const float *asrc, *adst, *aedge, *awe;
    float *fea;
    int N, E;
    // scratch
    float *ew, *deg, *h, *f1, *h2, *an_src, *an_dst, *att, *f2, *cvec, *ewsum;
    int *cnt, *rowptr, *cursor, *eid;
};
struct Pair { BP b[2]; };

static inline int cdiv(int a, int b) { return (a + b - 1) / b; }
static inline int pad4(int n) { return (n + 3) & ~3; }   // 16B-align float counts

// ---------------- init: deg=1 (self loop), cnt=0, ewsum=0 ----------------
__global__ void k_init(Pair P) {
    int i = blockIdx.x * blockDim.x + threadIdx.x;
    #pragma unroll
    for (int br = 0; br < 2; br++) {
        const BP& bp = P.b[br];
        if (i < bp.N) { bp.deg[i] = 1.0f; bp.cnt[i] = 0; }
        if (i == 0) bp.ewsum[0] = 0.f;
    }
}

// ------------- edge pass 1: gather ew, degree sum, histogram, ewsum -------------
__global__ void k_edge1(Pair P, int g0) {
    int br = blockIdx.x >= g0;
    const BP& bp = P.b[br];
    int base = (br ? (blockIdx.x - g0) : blockIdx.x) * 256;
    int e = base + threadIdx.x;
    float w = 0.f;
    if (e < bp.E) {
        int s = bp.edges[e], d = bp.edges[bp.E + e];
        w = bp.mat[s * bp.N + d];
        bp.ew[e] = w;
        atomicAdd(bp.deg + d, w);
        atomicAdd(bp.cnt + d, 1);
    }
    #pragma unroll
    for (int o = 16; o; o >>= 1) w += __shfl_down_sync(0xffffffffu, w, o);
    if ((threadIdx.x & 31) == 0 && w != 0.f) atomicAdd(bp.ewsum, w);
}

// ---------------- block scan -> rowptr/cursor, deg -> rsqrt ----------------
__global__ void k_scan(Pair P) {
    const BP& bp = P.b[blockIdx.x];
    __shared__ int sb[1024];
    int tid = threadIdx.x;
    int v = (tid < bp.N) ? bp.cnt[tid] : 0;
    sb[tid] = v;
    __syncthreads();
    #pragma unroll
    for (int off = 1; off < 1024; off <<= 1) {
        int t = (tid >= off) ? sb[tid - off] : 0;
        __syncthreads();
        sb[tid] += t;
        __syncthreads();
    }
    int incl = sb[tid];
    if (tid < bp.N) {
        bp.rowptr[tid + 1] = incl;
        bp.cursor[tid] = incl - v;
        bp.deg[tid] = rsqrtf(bp.deg[tid]);   // deg >= 1 always (self loop)
    }
    if (tid == 0) bp.rowptr[0] = 0;
}

// ---------------- edge pass 2: place edge ids into CSR ----------------
__global__ void k_edge2(Pair P, int g0) {
    int br = blockIdx.x >= g0;
    const BP& bp = P.b[br];
    int base = (br ? (blockIdx.x - g0) : blockIdx.x) * 256;
    int e = base + threadIdx.x;
    if (e < bp.E) {
        int d = bp.edges[bp.E + e];
        int pos = atomicAdd(bp.cursor + d, 1);
        bp.eid[pos] = e;
    }
}

// ---------------- tiled GEMM: C[M,Ncols] = A[M,128] @ W[128,Ncols] ----------------
__global__ void k_gemm128(const float* __restrict__ A0, const float* __restrict__ W0,
                          float* __restrict__ C0, int M0,
                          const float* __restrict__ A1, const float* __restrict__ W1,
                          float* __restrict__ C1, int M1, int Ncols) {
    int br = blockIdx.z;
    const float* A = br ? A1 : A0;
    const float* W = br ? W1 : W0;
    float* C = br ? C1 : C0;
    int M = br ? M1 : M0;
    int rb = blockIdx.y * 16;
    if (rb >= M) return;
    int col = blockIdx.x * 128 + threadIdx.x;
    __shared__ float sA[16 * 128];
    for (int idx = threadIdx.x; idx < 16 * 128; idx += 128) {
        int r = idx >> 7, k = idx & 127;
        sA[idx] = (rb + r < M) ? A[(rb + r) * 128 + k] : 0.f;
    }
    __syncthreads();
    float acc[16];
    #pragma unroll
    for (int r = 0; r < 16; r++) acc[r] = 0.f;
    #pragma unroll 4
    for (int k = 0; k < 128; k++) {
        float w = W[k * Ncols + col];
        #pragma unroll
        for (int r = 0; r < 16; r++) acc[r] = fmaf(sA[r * 128 + k], w, acc[r]);
    }
    #pragma unroll
    for (int r = 0; r < 16; r++)
        if (rb + r < M) C[(rb + r) * Ncols + col] = acc[r];
}

// ---------------- GCN gather: out = relu(b + h[d]*dinv^2 + sum h[s]*norm) ----------------
__global__ void k_gcn_gather(Pair P, int which) {
    int br = blockIdx.y;
    const BP& bp = P.b[br];
    int d = blockIdx.x;
    if (d >= bp.N) return;
    int j = threadIdx.x;  // 128
    const float* bias = which ? bp.gb2 : bp.gb1;
    float* out = which ? bp.f2 : bp.f1;
    const float* h = bp.h;
    float dd = bp.deg[d];
    float acc = fmaf(h[d * D + j], dd * dd, bias[j]);
    __shared__ int ssrc[128];
    __shared__ float snorm[128];
    int rp = bp.rowptr[d], re = bp.rowptr[d + 1];
    for (int base = rp; base < re; base += 128) {
        int c = base + j;
        if (c < re) {
            int e = bp.eid[c];
            int s = bp.edges[e];
            ssrc[j] = s;
            snorm[j] = bp.deg[s] * bp.ew[e] * dd;
        }
        __syncthreads();
        int cnt = min(128, re - base);
        for (int t = 0; t < cnt; t++)
            acc = fmaf(h[ssrc[t] * D + j], snorm[t], acc);
        __syncthreads();
    }
    out[d * D + j] = fmaxf(acc, 0.f);
}

// ---------------- attention node dots + edge-coef vector ----------------
__global__ void k_attn(Pair P) {
    int gw = (blockIdx.x * 256 + threadIdx.x) >> 5;
    int lane = threadIdx.x & 31;
    int n0 = P.b[0].N, n1 = P.b[1].N;
    int br, n = 0, hh;
    bool cv = false;
    if (gw < n0 * H) { br = 0; n = gw / H; hh = gw % H; }
    else if (gw < (n0 + n1) * H) { gw -= n0 * H; br = 1; n = gw / H; hh = gw % H; }
    else {
        gw -= (n0 + n1) * H;
        if (gw >= 2 * H) return;
        br = gw >= H; hh = gw & 7; cv = true;
    }
    const BP& bp = P.b[br];
    if (cv) {
        float4 a = ((const float4*)bp.awe)[hh * 32 + lane];
        float4 b = ((const float4*)bp.aedge)[hh * 32 + lane];
        float s = a.x * b.x + a.y * b.y + a.z * b.z + a.w * b.w;
        #pragma unroll
        for (int o = 16; o; o >>= 1) s += __shfl_down_sync(0xffffffffu, s, o);
        if (lane == 0) bp.cvec[hh] = s;
        return;
    }
    float4 v = ((const float4*)(bp.h2 + n * HD + hh * D))[lane];
    float4 as = ((const float4*)(bp.asrc + hh * D))[lane];
    float4 ad = ((const float4*)(bp.adst + hh * D))[lane];
    float s1 = v.x * as.x + v.y * as.y + v.z * as.z + v.w * as.w;
    float s2 = v.x * ad.x + v.y * ad.y + v.z * ad.z + v.w * ad.w;
    #pragma unroll
    for (int o = 16; o; o >>= 1) {
        s1 += __shfl_down_sync(0xffffffffu, s1, o);
        s2 += __shfl_down_sync(0xffffffffu, s2, o);
    }
    if (lane == 0) { bp.an_src[n * H + hh] = s1; bp.an_dst[n * H + hh] = s2; }
}

// ---------------- fused GAT: softmax + aggregate + head-mean + bias + relu ----------------
#define CH 128
__global__ void k_gat(Pair P) {
    int br = blockIdx.y;
    const BP& bp = P.b[br];
    int d = blockIdx.x;
    if (d >= bp.N) return;
    int tid = threadIdx.x, lane = tid & 31, wid = tid >> 5;  // wid = head 0..7
    __shared__ int ssrc[CH];
    __shared__ float sew[CH];
    __shared__ float scoef[8][CH];
    __shared__ float sm[8], sden[8], sc[8], sred[128];
    if (tid < 8) sc[tid] = bp.cvec[tid];
    float meanw = bp.ewsum[0] / (float)bp.E;
    int rp = bp.rowptr[d];
    int deg = bp.rowptr[d + 1] - rp;
    int total = deg + 1;  // + self loop
    __syncthreads();
    float adst = bp.an_dst[d * H + wid];
    float chh = sc[wid];

    // pass 1: online max / denominator per head (one warp per head)
    float m = -INFINITY, den = 0.f;
    for (int base = 0; base < total; base += CH) {
        int cnt = min(CH, total - base);
        if (tid < CH && base + tid < total) {
            int c = base + tid;
            if (c < deg) {
                int e = bp.eid[rp + c];
                ssrc[tid] = bp.edges[e];
                sew[tid] = bp.ew[e];
            } else { ssrc[tid] = d; sew[tid] = meanw; }
        }
        __syncthreads();
        float lg[4];
        int have = 0;
        float cm = -INFINITY;
        for (int c = lane; c < cnt; c += 32) {
            float l = bp.an_src[ssrc[c] * H + wid] + adst + sew[c] * chh;
            l = (l >= 0.f) ? l : 0.2f * l;
            lg[have++] = l;
            cm = fmaxf(cm, l);
        }
        #pragma unroll
        for (int o = 16; o; o >>= 1) cm = fmaxf(cm, __shfl_xor_sync(0xffffffffu, cm, o));
        float newm = fmaxf(m, cm);
        float ls = 0.f;
        for (int q = 0; q < have; q++) ls += __expf(lg[q] - newm);
        #pragma unroll
        for (int o = 16; o; o >>= 1) ls += __shfl_xor_sync(0xffffffffu, ls, o);
        den = den * __expf(m - newm) + ls;
        m = newm;
        __syncthreads();
    }
    if (lane == 0) { sm[wid] = m; sden[wid] = den + 1e-16f; }
    __syncthreads();

    // pass 2: coefficients + aggregation. Thread (half,j): heads half*4..+3, col j.
    int j = tid & 127;
    int hbase = (tid >> 7) * 4;
    float acc0 = 0.f, acc1 = 0.f, acc2 = 0.f, acc3 = 0.f;
    for (int base = 0; base < total; base += CH) {
        int cnt = min(CH, total - base);
        if (tid < CH && base + tid < total) {
            int c = base + tid;
            if (c < deg) {
                int e = bp.eid[rp + c];
                ssrc[tid] = bp.edges[e];
                sew[tid] = bp.ew[e];
            } else { ssrc[tid] = d; sew[tid] = meanw; }
        }
        __syncthreads();
        for (int c = lane; c < cnt; c += 32) {
            float l = bp.an_src[ssrc[c] * H + wid] + adst + sew[c] * chh;
            l = (l >= 0.f) ? l : 0.2f * l;
            scoef[wid][c] = __expf(l - sm[wid]) / sden[wid];
        }
        __syncthreads();
        for (int c = 0; c < cnt; c++) {
            const float* hr = bp.h2 + ssrc[c] * HD + hbase * D + j;
            acc0 = fmaf(hr[0],       scoef[hbase + 0][c], acc0);
            acc1 = fmaf(hr[D],       scoef[hbase + 1][c], acc1);
            acc2 = fmaf(hr[2 * D],   scoef[hbase + 2][c], acc2);
            acc3 = fmaf(hr[3 * D],   scoef[hbase + 3][c], acc3);
        }
        __syncthreads();
    }
    float part = acc0 + acc1 + acc2 + acc3;
    if (tid < 128) sred[j] = part;
    __syncthreads();
    if (tid >= 128) {
        float tot = sred[j] + part;
        bp.att[d * D + j] = fmaxf(fmaf(tot, 0.125f, bp.ab[j]), 0.f);
    }
}

// ---------------- CNN head: fea[n,o] = b[o] + W[o,0,:].f1[n] + W[o,1,:].f2[n] ----------------
__global__ void k_cnn(Pair P) {
    int br = blockIdx.z;
    const BP& bp = P.b[br];
    int rb = blockIdx.y * 16;
    if (rb >= bp.N) return;
    int o = blockIdx.x * 128 + threadIdx.x;
    __shared__ float sA[16 * 256];
    for (int idx = threadIdx.x; idx < 16 * 128; idx += 128) {
        int r = idx >> 7, k = idx & 127;
        int n = rb + r;
        sA[r * 256 + k] = (n < bp.N) ? bp.f1[n * D + k] : 0.f;
        sA[r * 256 + 128 + k] = (n < bp.N) ? bp.f2[n * D + k] : 0.f;
    }
    __syncthreads();
    float acc[16];
    float bo = bp.cb[o];
    #pragma unroll
    for (int r = 0; r < 16; r++) acc[r] = bo;
    const float* w = bp.cw + o * 256;
    #pragma unroll 4
    for (int k = 0; k < 256; k++) {
        float wv = w[k];
        #pragma unroll
        for (int r = 0; r < 16; r++) acc[r] = fmaf(sA[r * 256 + k], wv, acc[r]);
    }
    #pragma unroll
    for (int r = 0; r < 16; r++)
        if (rb + r < bp.N) bp.fea[(rb + r) * 256 + o] = acc[r];
}

// ---------------- final: out[i,j] = cir[i] . dis[j] ----------------
__global__ void k_final(const float* __restrict__ cir, const float* __restrict__ dis,
                        float* __restrict__ out) {
    int ib = blockIdx.x * 16;
    __shared__ float sc[16 * 256];
    for (int idx = threadIdx.x; idx < 16 * 256; idx += blockDim.x) {
        int i = ib + (idx >> 8);
        sc[idx] = (i < NCIR) ? cir[i * 256 + (idx & 255)] : 0.f;
    }
    __syncthreads();
    int j = threadIdx.x;
    if (j >= NDIS) return;
    float acc[16];
    #pragma unroll
    for (int r = 0; r < 16; r++) acc[r] = 0.f;
    const float* dr = dis + j * 256;
    #pragma unroll 4
    for (int k = 0; k < 256; k++) {
        float dv = dr[k];
        #pragma unroll
        for (int r = 0; r < 16; r++) acc[r] = fmaf(sc[r * 256 + k], dv, acc[r]);
    }
    #pragma unroll
    for (int r = 0; r < 16; r++)
        if (ib + r < NCIR) out[(ib + r) * NDIS + j] = acc[r];
}

// -------------------- host --------------------
static void fill_bp(BP& bp, const float* x, const float* mat, const int* edges,
                    const float* gb1, const float* asrc, const float* adst,
                    const float* aedge, const float* awe, const float* ab,
                    const float* gb2, const float* cw, const float* cb,
                    float* fea, int N, int E, float*& S) {
    bp.x = x; bp.mat = mat; bp.edges = edges;
    bp.gb1 = gb1; bp.asrc = asrc; bp.adst = adst; bp.aedge = aedge;
    bp.awe = awe; bp.ab = ab; bp.gb2 = gb2; bp.cw = cw; bp.cb = cb;
    bp.fea = fea; bp.N = N; bp.E = E;
    bp.ew = S;        S += pad4(E);
    bp.deg = S;       S += pad4(N);
    bp.h = S;         S += pad4(N * D);
    bp.f1 = S;        S += pad4(N * D);
    bp.h2 = S;        S += pad4(N * HD);
    bp.an_src = S;    S += pad4(N * H);
    bp.an_dst = S;    S += pad4(N * H);
    bp.att = S;       S += pad4(N * D);
    bp.f2 = S;        S += pad4(N * D);
    bp.cvec = S;      S += 8;
    bp.ewsum = S;     S += 8;
    bp.cnt = (int*)S;    S += pad4(N);
    bp.rowptr = (int*)S; S += pad4(N + 1);
    bp.cursor = (int*)S; S += pad4(N);
    bp.eid = (int*)S;    S += pad4(E);
}

extern "C" void kernel_launch(void* const* d_in, const int* in_sizes, int n_in,
                              void* d_out, int out_size) {
    float* S = nullptr;
    cudaGetSymbolAddress((void**)&S, g_scratch);

    const float* in_f[28];
    for (int i = 0; i < 28; i++) in_f[i] = (const float*)d_in[i];
    const int* cc_edges = (const int*)d_in[28];
    const int* dd_edges = (const int*)d_in[29];

    float* out = (float*)d_out;
    float* cirfea = out + NCIR * NDIS;
    float* disfea = cirfea + NCIR * 256;

    Pair P;
    float* cur = S;
    fill_bp(P.b[0], in_f[0], in_f[2], cc_edges,
            in_f[5], in_f[7], in_f[8], in_f[9], in_f[10], in_f[11],
            in_f[13], in_f[24], in_f[25], cirfea, NCIR, ECC, cur);
    fill_bp(P.b[1], in_f[1], in_f[3], dd_edges,
            in_f[15], in_f[17], in_f[18], in_f[19], in_f[20], in_f[21],
            in_f[23], in_f[26], in_f[27], disfea, NDIS, EDD, cur);

    const float* gw1_0 = in_f[4];
    const float* aw_0 = in_f[6];
    const float* gw2_0 = in_f[12];
    const float* gw1_1 = in_f[14];
    const float* aw_1 = in_f[16];
    const float* gw2_1 = in_f[22];

    int g0 = cdiv(ECC, 256), g1 = cdiv(EDD, 256);
    int ry = cdiv(NCIR, 16);  // 37, covers dis too

    k_init<<<cdiv(NCIR, 256), 256>>>(P);
    k_edge1<<<g0 + g1, 256>>>(P, g0);
    k_scan<<<2, 1024>>>(P);
    k_edge2<<<g0 + g1, 256>>>(P, g0);

    // GCN1
    k_gemm128<<<dim3(1, ry, 2), 128>>>(P.b[0].x, gw1_0, P.b[0].h, NCIR,
                                       P.b[1].x, gw1_1, P.b[1].h, NDIS, 128);
    k_gcn_gather<<<dim3(NCIR, 2), 128>>>(P, 0);

    // GAT
    k_gemm128<<<dim3(8, ry, 2), 128>>>(P.b[0].f1, aw_0, P.b[0].h2, NCIR,
                                       P.b[1].f1, aw_1, P.b[1].h2, NDIS, HD);
    int warps = (NCIR + NDIS + 2) * H;
    k_attn<<<cdiv(warps * 32, 256), 256>>>(P);
    k_gat<<<dim3(NCIR, 2), 256>>>(P);

    // GCN2
    k_gemm128<<<dim3(1, ry, 2), 128>>>(P.b[0].att, gw2_0, P.b[0].h, NCIR,
                                       P.b[1].att, gw2_1, P.b[1].h, NDIS, 128);
    k_gcn_gather<<<dim3(NCIR, 2), 128>>>(P, 1);

    // CNN heads + final matmul
    k_cnn<<<dim3(2, ry, 2), 128>>>(P);
    k_final<<<cdiv(NCIR, 16), 128>>>(cirfea, disfea, out);
}